// round 14
// baseline (speedup 1.0000x reference)
#include <cuda_runtime.h>
#include <cuda_bf16.h>
#include <math.h>

#define FULLMASK 0xFFFFFFFFu
#define NW 4              // warps per block, one matrix per warp
#define BITERS 8          // bisection iterations (err ~8e-5 << 1e-3 threshold)

// Compiler-only ordering fence for same-warp cross-lane smem traffic
// (all STS->LDS pairs sit in converged control flow).
#define WFENCE() asm volatile("" ::: "memory")

typedef unsigned long long ull;

__device__ double g_acc = 0.0;
__device__ unsigned int g_cnt = 0;

// Bank-balanced packed-triangular row offsets: float4-aligned, row i holds
// cols 0..i, and (RO[i] % 32) hits every bank exactly 4x -> column stores
// are 4-way (alignment floor) instead of 6-way conflicted.
__host__ __device__ constexpr int ro(int i) {
    constexpr int RO_TAB[32] = {
          0,   4,   8,  12,  16,  24,  52,  60,
         68,  80,  92, 104, 116, 140, 160, 184,
        200, 220, 240, 260, 280, 308, 332, 384,
        408, 436, 464, 492, 520, 572, 608, 644
    };
    return RO_TAB[i];
}
#define LP_SIZE 680   // row31 ends at 676, +overread pad

__device__ __forceinline__ float warp_sum(float v) {
    v += __shfl_xor_sync(FULLMASK, v, 16);
    v += __shfl_xor_sync(FULLMASK, v, 8);
    v += __shfl_xor_sync(FULLMASK, v, 4);
    v += __shfl_xor_sync(FULLMASK, v, 2);
    v += __shfl_xor_sync(FULLMASK, v, 1);
    return v;
}

__device__ __forceinline__ float frcp(float x) {
    float r; asm("rcp.approx.f32 %0, %1;" : "=f"(r) : "f"(x)); return r;
}
__device__ __forceinline__ float fsqrt_ap(float x) {
    float r; asm("sqrt.approx.f32 %0, %1;" : "=f"(r) : "f"(x)); return r;
}

// ---- packed f32x2 helpers (FFMA2 path; ptxas never emits it from C++) ----
__device__ __forceinline__ ull pk2(float lo, float hi) {
    ull r; asm("mov.b64 %0, {%1, %2};" : "=l"(r) : "f"(lo), "f"(hi)); return r;
}
__device__ __forceinline__ void upk2(ull v, float& lo, float& hi) {
    asm("mov.b64 {%0, %1}, %2;" : "=f"(lo), "=f"(hi) : "l"(v));
}
__device__ __forceinline__ ull pfma(ull a, ull b, ull c) {
    ull r; asm("fma.rn.f32x2 %0, %1, %2, %3;" : "=l"(r) : "l"(a), "l"(b), "l"(c));
    return r;
}

__global__ __launch_bounds__(NW * 32, 6)
void rdl_main(const float* __restrict__ X, const float* __restrict__ Y,
              float* __restrict__ out, int B) {
    const int lane = threadIdx.x & 31;
    const int wid  = threadIdx.x >> 5;
    const int mat  = blockIdx.x * NW + wid;

    __shared__ float Lp[NW][LP_SIZE];  // packed lower-tri L; reused for d/e later
    __shared__ float Bs[NW][32][33];   // transpose buffer; rows 0 and 4 reused u/w
    __shared__ float wsum[NW];

    float* lp = Lp[wid];
    float contrib = 0.0f;

    if (mat < B) {                     // warp-uniform (mat is per-warp)
        const float* xb = X + (size_t)mat * 1024;
        const float* yb = Y + (size_t)mat * 1024;

        // per-lane packed row offset (unrolled select -> pure registers)
        int rl = 0;
        #pragma unroll
        for (int i = 0; i < 32; ++i) if (lane == i) rl = ro(i);

        // ---- load Y column `lane` (== row, symmetric) ----
        float Lr[32];
        #pragma unroll
        for (int c = 0; c < 32; ++c) Lr[c] = yb[c * 32 + lane];

        // ---- Cholesky: row k of L broadcast from packed smem as float4 ----
        #pragma unroll
        for (int k = 0; k < 32; ++k) {
            WFENCE();
            float s0 = Lr[k], s1 = 0.f, s2 = 0.f, s3 = 0.f;
            #pragma unroll
            for (int g = 0; g * 4 < k; ++g) {
                float4 Lv = *(const float4*)(lp + ro(k) + g * 4);
                if (g*4+0 < k) s0 = fmaf(-Lr[g*4+0], Lv.x, s0);
                if (g*4+1 < k) s1 = fmaf(-Lr[g*4+1], Lv.y, s1);
                if (g*4+2 < k) s2 = fmaf(-Lr[g*4+2], Lv.z, s2);
                if (g*4+3 < k) s3 = fmaf(-Lr[g*4+3], Lv.w, s3);
            }
            float s   = (s0 + s1) + (s2 + s3);
            float skk = __shfl_sync(FULLMASK, s, k);
            float inv = rsqrtf(skk);
            float val = (lane == k) ? inv : s * inv;
            Lr[k] = val;
            if (lane >= k) lp[rl + k] = val;   // predicated packed column store
        }
        WFENCE();

        // ---- load X; PACKED forward solve L Z = X (thread = column) ----
        ull z2[16];
        {
            float xr[32];
            #pragma unroll
            for (int c = 0; c < 32; ++c) xr[c] = xb[c * 32 + lane];
            float prev = 0.0f;
            #pragma unroll
            for (int i = 0; i < 32; ++i) {
                const int ieven = i & ~1;
                ull  a0 = 0ull, a1 = 0ull;
                float s = xr[i];
                float inv = 0.0f;
                #pragma unroll
                for (int g = 0; g * 4 <= i; ++g) {
                    float4 Lv = *(const float4*)(lp + ro(i) + g * 4);
                    if (g*4+0 < ieven) a0 = pfma(pk2(Lv.x, Lv.y), z2[(g*4)>>1],   a0);
                    if (g*4+2 < ieven) a1 = pfma(pk2(Lv.z, Lv.w), z2[(g*4+2)>>1], a1);
                    if ((i & 1) && ((i - 1) >> 2) == g) {   // tail k = i-1 (odd i)
                        float Lt = ((i-1)&3)==0 ? Lv.x : ((i-1)&3)==1 ? Lv.y
                                 : ((i-1)&3)==2 ? Lv.z : Lv.w;
                        s = fmaf(-Lt, prev, s);
                    }
                    if ((i >> 2) == g)                       // diag (1/L[i][i])
                        inv = (i&3)==0 ? Lv.x : (i&3)==1 ? Lv.y
                            : (i&3)==2 ? Lv.z : Lv.w;
                }
                float b0, b1, b2, b3;
                upk2(a0, b0, b1); upk2(a1, b2, b3);
                s = (s - ((b0 + b1) + (b2 + b3))) * inv;
                if (i & 1) z2[i >> 1] = pk2(prev, s);
                prev = s;
            }
        }

        // ---- transpose Z ----
        #pragma unroll
        for (int t = 0; t < 16; ++t) {
            float a, b; upk2(z2[t], a, b);
            Bs[wid][lane][2*t]   = a;
            Bs[wid][lane][2*t+1] = b;
        }
        WFENCE();

        // ---- PACKED forward solve L M = Z^T  ->  M = L^{-1} X L^{-T} ----
        ull m2[16];
        {
            float prev = 0.0f;
            #pragma unroll
            for (int i = 0; i < 32; ++i) {
                const int ieven = i & ~1;
                ull  a0 = 0ull, a1 = 0ull;
                float s = Bs[wid][i][lane];
                float inv = 0.0f;
                #pragma unroll
                for (int g = 0; g * 4 <= i; ++g) {
                    float4 Lv = *(const float4*)(lp + ro(i) + g * 4);
                    if (g*4+0 < ieven) a0 = pfma(pk2(Lv.x, Lv.y), m2[(g*4)>>1],   a0);
                    if (g*4+2 < ieven) a1 = pfma(pk2(Lv.z, Lv.w), m2[(g*4+2)>>1], a1);
                    if ((i & 1) && ((i - 1) >> 2) == g) {
                        float Lt = ((i-1)&3)==0 ? Lv.x : ((i-1)&3)==1 ? Lv.y
                                 : ((i-1)&3)==2 ? Lv.z : Lv.w;
                        s = fmaf(-Lt, prev, s);
                    }
                    if ((i >> 2) == g)
                        inv = (i&3)==0 ? Lv.x : (i&3)==1 ? Lv.y
                            : (i&3)==2 ? Lv.z : Lv.w;
                }
                float b0, b1, b2, b3;
                upk2(a0, b0, b1); upk2(a1, b2, b3);
                s = (s - ((b0 + b1) + (b2 + b3))) * inv;
                if (i & 1) m2[i >> 1] = pk2(prev, s);
                prev = s;
            }
        }
        WFENCE();   // Lp dead as L from here -> reuse for d / e

        float* d_sh = lp;        // [32] diag of T     (16B aligned)
        float* e_sh = lp + 32;   // [32] off-diag of T (16B aligned)

        // ---- Householder tridiag on packed m2; unnormalized reflector
        //      u = x - beta*e1, tau = 2/||u||^2 (r11 form: one u store). ----
        float* u_sh = &Bs[wid][0][0];   // 16B aligned, contiguous
        float* w_sh = &Bs[wid][4][0];   // 16B aligned, contiguous
        #pragma unroll
        for (int k = 0; k < 30; ++k) {
            float mlo, mhi; upk2(m2[k >> 1], mlo, mhi);
            float xk_raw = (k & 1) ? mhi : mlo;          // m[k] of this lane
            float xk     = (lane > k) ? xk_raw : 0.0f;
            float alpha  = __shfl_sync(FULLMASK, xk_raw, k + 1);
            float sigma  = warp_sum((lane > k + 1) ? xk * xk : 0.0f);

            float mu    = fsqrt_ap(fmaf(alpha, alpha, sigma));
            float beta  = (alpha >= 0.0f) ? -mu : mu;
            float ab    = alpha - beta;
            float tau   = __fdividef(2.0f, fmaf(ab, ab, sigma));  // 2/||u||^2
            float u     = (lane == k + 1) ? ab : xk;
            if (sigma <= 1e-12f) { beta = alpha; tau = 0.0f; u = 0.0f; }  // uniform
            if (lane == k) { d_sh[k] = xk_raw; e_sh[k] = beta; }  // row k final
            u_sh[lane] = u;
            WFENCE();

            // p = tau * A u, packed (u_j == 0 for j <= k -> over-range exact)
            ull acc0 = 0ull, acc1 = 0ull;
            #pragma unroll
            for (int g = (k + 1) & ~3; g < 32; g += 4) {
                float4 uu = *(const float4*)&u_sh[g];
                acc0 = pfma(m2[g >> 1],       pk2(uu.x, uu.y), acc0);
                acc1 = pfma(m2[(g >> 1) + 1], pk2(uu.z, uu.w), acc1);
            }
            float b0, b1, b2, b3;
            upk2(acc0, b0, b1); upk2(acc1, b2, b3);
            float p = ((b0 + b1) + (b2 + b3)) * tau;

            float dot = tau * warp_sum(p * u);
            float w   = fmaf(-0.5f * dot, u, p);
            w_sh[lane] = w;
            WFENCE();

            // trailing update packed: A <- A - u w^T - w u^T
            ull nu2 = pk2(-u, -u), nw2 = pk2(-w, -w);
            #pragma unroll
            for (int g = (k + 1) & ~3; g < 32; g += 4) {
                float4 uu = *(const float4*)&u_sh[g];
                float4 ww = *(const float4*)&w_sh[g];
                int t = g >> 1;
                m2[t]   = pfma(nu2, pk2(ww.x, ww.y), pfma(nw2, pk2(uu.x, uu.y), m2[t]));
                m2[t+1] = pfma(nu2, pk2(ww.z, ww.w), pfma(nw2, pk2(uu.z, uu.w), m2[t+1]));
            }
        }
        {
            float mlo, mhi; upk2(m2[15], mlo, mhi);      // {m[30], m[31]}
            if (lane == 30) { d_sh[30] = mlo; e_sh[30] = mhi; }  // e[30]=M[31][30]
            if (lane == 31) { d_sh[31] = mhi; e_sh[31] = 0.0f; }
        }
        WFENCE();

        // ---- Gershgorin: per-lane row radius, 10-shfl min/max reduce ----
        float d_l = d_sh[lane];
        float ev  = (lane < 31) ? e_sh[lane] : 0.f;
        float em  = (lane > 0)  ? e_sh[lane - 1] : 0.f;
        float r   = fabsf(em) + fabsf(ev);
        float gl  = d_l - r, gh = d_l + r;
        #pragma unroll
        for (int o = 16; o > 0; o >>= 1) {
            gl = fminf(gl, __shfl_xor_sync(FULLMASK, gl, o));
            gh = fmaxf(gh, __shfl_xor_sync(FULLMASK, gh, o));
        }
        float span = gh - gl;
        float lo = gl - 1e-4f * span - 1e-6f;
        float hi = gh + 1e-4f * span + 1e-6f;

        // ---- pull T into registers via one-time float4 broadcasts ----
        float d[32], e2[31];
        #pragma unroll
        for (int g = 0; g < 8; ++g) {
            float4 dd = *(const float4*)&d_sh[g * 4];
            d[g*4+0] = dd.x; d[g*4+1] = dd.y; d[g*4+2] = dd.z; d[g*4+3] = dd.w;
        }
        #pragma unroll
        for (int g = 0; g < 8; ++g) {
            float4 ee = *(const float4*)&e_sh[g * 4];
            if (g*4+0 < 31) e2[g*4+0] = fmaxf(ee.x * ee.x, 1e-28f);
            if (g*4+1 < 31) e2[g*4+1] = fmaxf(ee.y * ee.y, 1e-28f);
            if (g*4+2 < 31) e2[g*4+2] = fmaxf(ee.z * ee.z, 1e-28f);
            if (g*4+3 < 31) e2[g*4+3] = fmaxf(ee.w * ee.w, 1e-28f);
        }

        // ---- Sturm bisection, TWISTED factorization, twist r = 16 ----
        #pragma unroll 1
        for (int it = 0; it < BITERS; ++it) {
            float mid = 0.5f * (lo + hi);
            float q = d[0]  - mid;                    // fwd pivot, row 0
            float p = d[31] - mid;                    // bwd pivot, row 31
            int   c = (__float_as_int(q) >> 31) + (__float_as_int(p) >> 31);
            #pragma unroll
            for (int i = 1; i < 16; ++i) {
                q  = fmaf(-e2[i - 1], frcp(q), d[i] - mid);            // rows 1..15
                c += __float_as_int(q) >> 31;
                if (i < 15) {
                    p  = fmaf(-e2[31 - i], frcp(p), d[31 - i] - mid);  // rows 30..17
                    c += __float_as_int(p) >> 31;
                }
            }
            // twist pivot: gamma_16 = d16 - mid - e2_15/q_15 - e2_16/p_17
            float g16 = fmaf(-e2[15], frcp(q), fmaf(-e2[16], frcp(p), d[16] - mid));
            c += __float_as_int(g16) >> 31;
            bool up = (c + lane >= 0);                // count(<mid) <= lane
            lo = up ? mid : lo;
            hi = up ? hi  : mid;
        }
        float lam = fmaxf(0.5f * (lo + hi), 1e-20f);
        float lg  = __logf(lam);
        contrib   = fsqrt_ap(warp_sum(lg * lg));
    }

    // ---- block reduce + last-block finalize ----
    if (lane == 0) wsum[wid] = contrib;
    __syncthreads();
    if (threadIdx.x == 0) {
        double s = ((double)wsum[0] + (double)wsum[1])
                 + ((double)wsum[2] + (double)wsum[3]);
        atomicAdd(&g_acc, s);
        __threadfence();
        unsigned t = atomicAdd(&g_cnt, 1u);
        if (t == gridDim.x - 1) {
            __threadfence();
            out[0] = (float)(g_acc / (double)B);
            g_acc = 0.0;
            g_cnt = 0u;
        }
    }
}

extern "C" void kernel_launch(void* const* d_in, const int* in_sizes, int n_in,
                              void* d_out, int out_size) {
    const float* x = (const float*)d_in[0];
    const float* y = (const float*)d_in[1];
    int B = in_sizes[0] / 1024;
    float* out = (float*)d_out;

    int blocks = (B + NW - 1) / NW;
    rdl_main<<<blocks, NW * 32>>>(x, y, out, B);
}

// round 15
// speedup vs baseline: 1.0282x; 1.0282x over previous
#include <cuda_runtime.h>
#include <cuda_bf16.h>
#include <math.h>

#define FULLMASK 0xFFFFFFFFu
#define NW 4              // warps per block, one matrix per warp
#define BITERS 7          // bisection iterations (err ~2.7e-4 < 1e-3 threshold)

// Compiler-only ordering fence for same-warp cross-lane smem traffic
// (all STS->LDS pairs sit in converged control flow).
#define WFENCE() asm volatile("" ::: "memory")

typedef unsigned long long ull;

__device__ double g_acc = 0.0;
__device__ unsigned int g_cnt = 0;

// packed-triangular row offset: float4-aligned, gap(i) >= i+1
__host__ __device__ constexpr int ro(int i) {
    return (i * (i + 1) / 2 + 3 * i + 3) & ~3;
}
#define LP_SIZE 640

__device__ __forceinline__ float warp_sum(float v) {
    v += __shfl_xor_sync(FULLMASK, v, 16);
    v += __shfl_xor_sync(FULLMASK, v, 8);
    v += __shfl_xor_sync(FULLMASK, v, 4);
    v += __shfl_xor_sync(FULLMASK, v, 2);
    v += __shfl_xor_sync(FULLMASK, v, 1);
    return v;
}

__device__ __forceinline__ float frcp(float x) {
    float r; asm("rcp.approx.f32 %0, %1;" : "=f"(r) : "f"(x)); return r;
}
__device__ __forceinline__ float fsqrt_ap(float x) {
    float r; asm("sqrt.approx.f32 %0, %1;" : "=f"(r) : "f"(x)); return r;
}

// ---- packed f32x2 helpers (FFMA2 path; ptxas never emits it from C++) ----
__device__ __forceinline__ ull pk2(float lo, float hi) {
    ull r; asm("mov.b64 %0, {%1, %2};" : "=l"(r) : "f"(lo), "f"(hi)); return r;
}
__device__ __forceinline__ void upk2(ull v, float& lo, float& hi) {
    asm("mov.b64 {%0, %1}, %2;" : "=f"(lo), "=f"(hi) : "l"(v));
}
__device__ __forceinline__ ull pfma(ull a, ull b, ull c) {
    ull r; asm("fma.rn.f32x2 %0, %1, %2, %3;" : "=l"(r) : "l"(a), "l"(b), "l"(c));
    return r;
}

__global__ __launch_bounds__(NW * 32, 6)
void rdl_main(const float* __restrict__ X, const float* __restrict__ Y,
              float* __restrict__ out, int B) {
    const int lane = threadIdx.x & 31;
    const int wid  = threadIdx.x >> 5;
    const int mat  = blockIdx.x * NW + wid;

    __shared__ float Lp[NW][LP_SIZE];  // packed lower-tri L; reused for d/e later
    __shared__ float Bs[NW][32][33];   // transpose buffer; rows 0 and 4 reused u/w
    __shared__ float wsum[NW];

    float* lp = Lp[wid];
    float contrib = 0.0f;

    if (mat < B) {                     // warp-uniform (mat is per-warp)
        const float* xb = X + (size_t)mat * 1024;
        const float* yb = Y + (size_t)mat * 1024;

        const int rl = ((lane * (lane + 1)) / 2 + 3 * lane + 3) & ~3;

        // ---- load Y column `lane` (== row, symmetric) and X column `lane` ----
        float Lr[32], xz[32];
        #pragma unroll
        for (int c = 0; c < 32; ++c) Lr[c] = yb[c * 32 + lane];
        #pragma unroll
        for (int c = 0; c < 32; ++c) xz[c] = xb[c * 32 + lane];

        // ---- FUSED Cholesky + forward solve L Z = X (in place on xz).
        //      Step k reads row k of L from packed smem ONCE (float4
        //      broadcasts); the same Lv registers feed both the Cholesky
        //      dot (vs lane's own row Lr) and the substitution dot
        //      (vs finalized z entries). inv = 1/L(k,k) is in every lane. ----
        #pragma unroll
        for (int k = 0; k < 32; ++k) {
            WFENCE();
            float s0 = Lr[k], s1 = 0.f, s2 = 0.f, s3 = 0.f;
            float t0 = 0.f,  t1 = 0.f, t2 = 0.f, t3 = 0.f;
            #pragma unroll
            for (int g = 0; g * 4 < k; ++g) {
                float4 Lv = *(const float4*)(lp + ro(k) + g * 4);
                if (g*4+0 < k) { s0 = fmaf(-Lr[g*4+0], Lv.x, s0); t0 = fmaf(Lv.x, xz[g*4+0], t0); }
                if (g*4+1 < k) { s1 = fmaf(-Lr[g*4+1], Lv.y, s1); t1 = fmaf(Lv.y, xz[g*4+1], t1); }
                if (g*4+2 < k) { s2 = fmaf(-Lr[g*4+2], Lv.z, s2); t2 = fmaf(Lv.z, xz[g*4+2], t2); }
                if (g*4+3 < k) { s3 = fmaf(-Lr[g*4+3], Lv.w, s3); t3 = fmaf(Lv.w, xz[g*4+3], t3); }
            }
            float s   = (s0 + s1) + (s2 + s3);
            float skk = __shfl_sync(FULLMASK, s, k);
            float inv = rsqrtf(skk);
            float val = (lane == k) ? inv : s * inv;
            Lr[k] = val;
            if (lane >= k) lp[rl + k] = val;             // packed column store
            xz[k] = (xz[k] - ((t0 + t1) + (t2 + t3))) * inv;   // z_k finalized
        }
        WFENCE();

        // ---- transpose Z ----
        #pragma unroll
        for (int i = 0; i < 32; ++i) Bs[wid][lane][i] = xz[i];
        WFENCE();

        // ---- PACKED forward solve L M = Z^T  ->  M = L^{-1} X L^{-T} ----
        ull m2[16];
        {
            float prev = 0.0f;
            #pragma unroll
            for (int i = 0; i < 32; ++i) {
                const int ieven = i & ~1;
                ull  a0 = 0ull, a1 = 0ull;
                float s = Bs[wid][i][lane];
                float inv = 0.0f;
                #pragma unroll
                for (int g = 0; g * 4 <= i; ++g) {
                    float4 Lv = *(const float4*)(lp + ro(i) + g * 4);
                    if (g*4+0 < ieven) a0 = pfma(pk2(Lv.x, Lv.y), m2[(g*4)>>1],   a0);
                    if (g*4+2 < ieven) a1 = pfma(pk2(Lv.z, Lv.w), m2[(g*4+2)>>1], a1);
                    if ((i & 1) && ((i - 1) >> 2) == g) {   // tail k = i-1 (odd i)
                        float Lt = ((i-1)&3)==0 ? Lv.x : ((i-1)&3)==1 ? Lv.y
                                 : ((i-1)&3)==2 ? Lv.z : Lv.w;
                        s = fmaf(-Lt, prev, s);
                    }
                    if ((i >> 2) == g)                       // diag (1/L[i][i])
                        inv = (i&3)==0 ? Lv.x : (i&3)==1 ? Lv.y
                            : (i&3)==2 ? Lv.z : Lv.w;
                }
                float b0, b1, b2, b3;
                upk2(a0, b0, b1); upk2(a1, b2, b3);
                s = (s - ((b0 + b1) + (b2 + b3))) * inv;
                if (i & 1) m2[i >> 1] = pk2(prev, s);
                prev = s;
            }
        }
        WFENCE();   // Lp dead as L from here -> reuse for d / e

        float* d_sh = lp;        // [32] diag of T     (16B aligned)
        float* e_sh = lp + 32;   // [32] off-diag of T (16B aligned)

        // ---- Householder tridiag on packed m2 (overlapped r13 form):
        //      A*u = A*x - beta*A[:,k+1]; matvec on x overlaps sigma. ----
        float* u_sh = &Bs[wid][0][0];   // 16B aligned, contiguous
        float* w_sh = &Bs[wid][4][0];   // 16B aligned, contiguous
        #pragma unroll
        for (int k = 0; k < 30; ++k) {
            float mlo, mhi; upk2(m2[k >> 1], mlo, mhi);
            float xk_raw = (k & 1) ? mhi : mlo;          // m[k] of this lane
            float xk     = (lane > k) ? xk_raw : 0.0f;   // x vector
            u_sh[lane] = xk;                             // store x NOW
            WFENCE();

            float alpha  = __shfl_sync(FULLMASK, xk_raw, k + 1);
            float sigma  = warp_sum((lane > k + 1) ? xk * xk : 0.0f);

            // y1 = A x  (independent of sigma -> overlaps the shfl chain)
            ull acc0 = 0ull, acc1 = 0ull;
            #pragma unroll
            for (int g = (k + 1) & ~3; g < 32; g += 4) {
                float4 uu = *(const float4*)&u_sh[g];
                acc0 = pfma(m2[g >> 1],       pk2(uu.x, uu.y), acc0);
                acc1 = pfma(m2[(g >> 1) + 1], pk2(uu.z, uu.w), acc1);
            }
            float b0, b1, b2, b3;
            upk2(acc0, b0, b1); upk2(acc1, b2, b3);
            float y1 = (b0 + b1) + (b2 + b3);

            float mu    = fsqrt_ap(fmaf(alpha, alpha, sigma));
            float beta  = (alpha >= 0.0f) ? -mu : mu;
            float ab    = alpha - beta;
            float tau   = __fdividef(2.0f, fmaf(ab, ab, sigma));  // 2/||u||^2
            if (sigma <= 1e-12f) { beta = alpha; ab = 0.0f; tau = 0.0f; }
            if (lane == k) { d_sh[k] = xk_raw; e_sh[k] = beta; }  // row k final

            // column k+1 of A for this lane (register)
            float nlo, nhi; upk2(m2[(k + 1) >> 1], nlo, nhi);
            float mk1 = ((k + 1) & 1) ? nhi : nlo;

            float u = (lane == k + 1) ? ab : xk;
            float p = tau * fmaf(-beta, mk1, y1);        // tau * (A u)_lane

            float dot = tau * warp_sum(p * u);           // frozen lanes: u=0 masks p junk
            float w   = fmaf(-0.5f * dot, u, p);
            w_sh[lane] = w;
            if (lane == k + 1) u_sh[lane] = ab;          // patch x -> u (after matvec reads)
            WFENCE();

            // trailing update packed: A <- A - u w^T - w u^T
            ull nu2 = pk2(-u, -u), nw2 = pk2(-w, -w);
            #pragma unroll
            for (int g = (k + 1) & ~3; g < 32; g += 4) {
                float4 uu = *(const float4*)&u_sh[g];
                float4 ww = *(const float4*)&w_sh[g];
                int t = g >> 1;
                m2[t]   = pfma(nu2, pk2(ww.x, ww.y), pfma(nw2, pk2(uu.x, uu.y), m2[t]));
                m2[t+1] = pfma(nu2, pk2(ww.z, ww.w), pfma(nw2, pk2(uu.z, uu.w), m2[t+1]));
            }
        }
        {
            float mlo, mhi; upk2(m2[15], mlo, mhi);      // {m[30], m[31]}
            if (lane == 30) { d_sh[30] = mlo; e_sh[30] = mhi; }  // e[30]=M[31][30]
            if (lane == 31) { d_sh[31] = mhi; e_sh[31] = 0.0f; }
        }
        WFENCE();

        // ---- Gershgorin: per-lane row radius, 10-shfl min/max reduce ----
        float d_l = d_sh[lane];
        float ev  = (lane < 31) ? e_sh[lane] : 0.f;
        float em  = (lane > 0)  ? e_sh[lane - 1] : 0.f;
        float r   = fabsf(em) + fabsf(ev);
        float gl  = d_l - r, gh = d_l + r;
        #pragma unroll
        for (int o = 16; o > 0; o >>= 1) {
            gl = fminf(gl, __shfl_xor_sync(FULLMASK, gl, o));
            gh = fmaxf(gh, __shfl_xor_sync(FULLMASK, gh, o));
        }
        float span = gh - gl;
        float lo = gl - 1e-4f * span - 1e-6f;
        float hi = gh + 1e-4f * span + 1e-6f;

        // ---- pull T into registers via one-time float4 broadcasts ----
        float d[32], e2[31];
        #pragma unroll
        for (int g = 0; g < 8; ++g) {
            float4 dd = *(const float4*)&d_sh[g * 4];
            d[g*4+0] = dd.x; d[g*4+1] = dd.y; d[g*4+2] = dd.z; d[g*4+3] = dd.w;
        }
        #pragma unroll
        for (int g = 0; g < 8; ++g) {
            float4 ee = *(const float4*)&e_sh[g * 4];
            if (g*4+0 < 31) e2[g*4+0] = fmaxf(ee.x * ee.x, 1e-28f);
            if (g*4+1 < 31) e2[g*4+1] = fmaxf(ee.y * ee.y, 1e-28f);
            if (g*4+2 < 31) e2[g*4+2] = fmaxf(ee.z * ee.z, 1e-28f);
            if (g*4+3 < 31) e2[g*4+3] = fmaxf(ee.w * ee.w, 1e-28f);
        }

        // ---- Sturm bisection, TWISTED factorization, twist r = 16 ----
        #pragma unroll 1
        for (int it = 0; it < BITERS; ++it) {
            float mid = 0.5f * (lo + hi);
            float q = d[0]  - mid;                    // fwd pivot, row 0
            float p = d[31] - mid;                    // bwd pivot, row 31
            int   c = (__float_as_int(q) >> 31) + (__float_as_int(p) >> 31);
            #pragma unroll
            for (int i = 1; i < 16; ++i) {
                q  = fmaf(-e2[i - 1], frcp(q), d[i] - mid);            // rows 1..15
                c += __float_as_int(q) >> 31;
                if (i < 15) {
                    p  = fmaf(-e2[31 - i], frcp(p), d[31 - i] - mid);  // rows 30..17
                    c += __float_as_int(p) >> 31;
                }
            }
            // twist pivot: gamma_16 = d16 - mid - e2_15/q_15 - e2_16/p_17
            float g16 = fmaf(-e2[15], frcp(q), fmaf(-e2[16], frcp(p), d[16] - mid));
            c += __float_as_int(g16) >> 31;
            bool up = (c + lane >= 0);                // count(<mid) <= lane
            lo = up ? mid : lo;
            hi = up ? hi  : mid;
        }
        float lam = fmaxf(0.5f * (lo + hi), 1e-20f);
        float lg  = __logf(lam);
        contrib   = fsqrt_ap(warp_sum(lg * lg));
    }

    // ---- block reduce + last-block finalize ----
    if (lane == 0) wsum[wid] = contrib;
    __syncthreads();
    if (threadIdx.x == 0) {
        double s = ((double)wsum[0] + (double)wsum[1])
                 + ((double)wsum[2] + (double)wsum[3]);
        atomicAdd(&g_acc, s);
        __threadfence();
        unsigned t = atomicAdd(&g_cnt, 1u);
        if (t == gridDim.x - 1) {
            __threadfence();
            out[0] = (float)(g_acc / (double)B);
            g_acc = 0.0;
            g_cnt = 0u;
        }
    }
}

extern "C" void kernel_launch(void* const* d_in, const int* in_sizes, int n_in,
                              void* d_out, int out_size) {
    const float* x = (const float*)d_in[0];
    const float* y = (const float*)d_in[1];
    int B = in_sizes[0] / 1024;
    float* out = (float*)d_out;

    int blocks = (B + NW - 1) / NW;
    rdl_main<<<blocks, NW * 32>>>(x, y, out, B);
}